// round 1
// baseline (speedup 1.0000x reference)
#include <cuda_runtime.h>

// Problem constants (from reference)
#define G_ 4096
#define U_ 50
#define M_ 20
#define D_ 64
#define S_ 64
#define FACTOR_ 0.5f

#define NWARPS 16
#define NTHREADS (NWARPS * 32)

__global__ __launch_bounds__(NTHREADS)
void group_embedding_kernel(const int*   __restrict__ group_user,      // [G,U]
                            const int*   __restrict__ behavior_ids,    // [G,U,M]
                            const float* __restrict__ behavior_counts, // [G,U,M]
                            const int*   __restrict__ target_user,     // [G]
                            const float* __restrict__ similarity_vec,  // [100000,S]
                            const float* __restrict__ user_emb_w,      // [100000,D]
                            const float* __restrict__ item_emb_w,      // [100000,D]
                            float*       __restrict__ out)             // [G,D]
{
    const int g    = blockIdx.x;
    const int tid  = threadIdx.x;
    const int warp = tid >> 5;
    const int lane = tid & 31;

    __shared__ float partials[NWARPS][D_];

    // Target similarity vector for this group: each lane holds 2 consecutive dims.
    const int tgt = target_user[g];
    const float2 tsim = *reinterpret_cast<const float2*>(
        similarity_vec + (size_t)tgt * S_ + 2 * lane);

    float2 acc = make_float2(0.f, 0.f);

    for (int u = warp; u < U_; u += NWARPS) {
        const int uid = group_user[g * U_ + u];

        // sim = FACTOR * dot(target_sim, other_sim)
        const float2 osim = *reinterpret_cast<const float2*>(
            similarity_vec + (size_t)uid * S_ + 2 * lane);
        float dot = tsim.x * osim.x + tsim.y * osim.y;
        #pragma unroll
        for (int o = 16; o; o >>= 1)
            dot += __shfl_xor_sync(0xffffffffu, dot, o);
        const float sim = FACTOR_ * dot;

        // Behavior ids/counts: lanes 0..19 load one pair, broadcast via shfl.
        const int base = (g * U_ + u) * M_;
        int   myid = 0;
        float myc  = 0.f;
        if (lane < M_) {
            myid = behavior_ids[base + lane];
            myc  = behavior_counts[base + lane];
        }

        // Weighted sum of item embeddings (the big gather).
        float2 ub = make_float2(0.f, 0.f);
        #pragma unroll
        for (int m = 0; m < M_; m++) {
            const int   id = __shfl_sync(0xffffffffu, myid, m);
            const float c  = __shfl_sync(0xffffffffu, myc,  m);
            const float2 e = *reinterpret_cast<const float2*>(
                item_emb_w + (size_t)id * D_ + 2 * lane);
            ub.x += e.x * c;
            ub.y += e.y * c;
        }

        // Personalize with user embedding, weight by sim, accumulate over users.
        const float2 ue = *reinterpret_cast<const float2*>(
            user_emb_w + (size_t)uid * D_ + 2 * lane);
        acc.x += ub.x * ue.x * sim;
        acc.y += ub.y * ue.y * sim;
    }

    partials[warp][2 * lane]     = acc.x;
    partials[warp][2 * lane + 1] = acc.y;
    __syncthreads();

    // Deterministic cross-warp tree sum: threads 0..63 each own one dim.
    if (tid < D_) {
        float s = 0.f;
        #pragma unroll
        for (int w = 0; w < NWARPS; w++)
            s += partials[w][tid];
        out[(size_t)g * D_ + tid] = s;
    }
}

extern "C" void kernel_launch(void* const* d_in, const int* in_sizes, int n_in,
                              void* d_out, int out_size) {
    const int*   group_user      = (const int*)  d_in[0];
    const int*   behavior_ids    = (const int*)  d_in[1];
    const float* behavior_counts = (const float*)d_in[2];
    const int*   target_user     = (const int*)  d_in[3];
    const float* similarity_vec  = (const float*)d_in[4];
    const float* user_emb_w      = (const float*)d_in[5];
    const float* item_emb_w      = (const float*)d_in[6];
    float* out = (float*)d_out;

    group_embedding_kernel<<<G_, NTHREADS>>>(
        group_user, behavior_ids, behavior_counts, target_user,
        similarity_vec, user_emb_w, item_emb_w, out);
}

// round 3
// speedup vs baseline: 1.3070x; 1.3070x over previous
#include <cuda_runtime.h>

// Problem constants (from reference)
#define G_ 4096
#define U_ 50
#define M_ 20
#define D_ 64
#define S_ 64
#define FACTOR_ 0.5f

#define NWARPS 16
#define NTHREADS (NWARPS * 32)
#define SLOTS (NWARPS * 2)   // 32 half-warp user slots per pass

__global__ __launch_bounds__(NTHREADS)
void group_embedding_kernel(const int*   __restrict__ group_user,      // [G,U]
                            const int*   __restrict__ behavior_ids,    // [G,U,M]
                            const float* __restrict__ behavior_counts, // [G,U,M]
                            const int*   __restrict__ target_user,     // [G]
                            const float* __restrict__ similarity_vec,  // [100000,S]
                            const float* __restrict__ user_emb_w,      // [100000,D]
                            const float* __restrict__ item_emb_w,      // [100000,D]
                            float*       __restrict__ out)             // [G,D]
{
    const int g    = blockIdx.x;
    const int tid  = threadIdx.x;
    const int warp = tid >> 5;
    const int lane = tid & 31;
    const int half = lane >> 4;     // which user of the pair
    const int hl   = lane & 15;     // lane within half-warp: owns dims 4*hl..4*hl+3

    // 16B alignment is required for the float4 stores into partials.
    __shared__ __align__(16) float  partials[SLOTS][D_]; // 8KB
    __shared__ __align__(16) float2 beh[U_ * M_];        // packed (id_as_float, count), 8KB
    __shared__ int    uid_s[U_];                          // group user ids

    // ---- Stage per-group metadata into smem (coalesced) ----
    {
        const int base = g * (U_ * M_);
        for (int i = tid; i < U_ * M_; i += NTHREADS) {
            beh[i] = make_float2(__int_as_float(behavior_ids[base + i]),
                                 behavior_counts[base + i]);
        }
        if (tid < U_) uid_s[tid] = group_user[g * U_ + tid];
    }
    __syncthreads();

    // Target similarity vector: each half-lane holds 4 consecutive dims.
    const int tgt = target_user[g];
    const float4 tsim = *reinterpret_cast<const float4*>(
        similarity_vec + (size_t)tgt * S_ + 4 * hl);

    float4 acc = make_float4(0.f, 0.f, 0.f, 0.f);

    const int slot = warp * 2 + half;   // 0..31

    for (int u = slot; u < U_; u += SLOTS) {
        const int uid = uid_s[u];

        // sim = FACTOR * dot(target_sim, other_sim), reduced over the half-warp
        const float4 osim = *reinterpret_cast<const float4*>(
            similarity_vec + (size_t)uid * S_ + 4 * hl);
        float dot = tsim.x * osim.x + tsim.y * osim.y
                  + tsim.z * osim.z + tsim.w * osim.w;
        #pragma unroll
        for (int o = 8; o; o >>= 1)
            dot += __shfl_xor_sync(0xffffffffu, dot, o);
        const float sim = FACTOR_ * dot;

        // Weighted sum of item embeddings: 20 independent float4 gathers.
        float4 ub = make_float4(0.f, 0.f, 0.f, 0.f);
        const int bbase = u * M_;
        #pragma unroll
        for (int m = 0; m < M_; m++) {
            const float2 p  = beh[bbase + m];       // LDS.64 broadcast per half
            const int    id = __float_as_int(p.x);
            const float  c  = p.y;
            const float4 e  = *reinterpret_cast<const float4*>(
                item_emb_w + (size_t)id * D_ + 4 * hl);
            ub.x += e.x * c;  ub.y += e.y * c;
            ub.z += e.z * c;  ub.w += e.w * c;
        }

        // Personalize with user embedding, weight by sim, accumulate.
        const float4 ue = *reinterpret_cast<const float4*>(
            user_emb_w + (size_t)uid * D_ + 4 * hl);
        acc.x += ub.x * ue.x * sim;
        acc.y += ub.y * ue.y * sim;
        acc.z += ub.z * ue.z * sim;
        acc.w += ub.w * ue.w * sim;
    }

    *reinterpret_cast<float4*>(&partials[slot][4 * hl]) = acc;
    __syncthreads();

    // Deterministic cross-slot tree sum: threads 0..63 each own one dim.
    if (tid < D_) {
        float s = 0.f;
        #pragma unroll
        for (int w = 0; w < SLOTS; w++)
            s += partials[w][tid];
        out[(size_t)g * D_ + tid] = s;
    }
}

extern "C" void kernel_launch(void* const* d_in, const int* in_sizes, int n_in,
                              void* d_out, int out_size) {
    const int*   group_user      = (const int*)  d_in[0];
    const int*   behavior_ids    = (const int*)  d_in[1];
    const float* behavior_counts = (const float*)d_in[2];
    const int*   target_user     = (const int*)  d_in[3];
    const float* similarity_vec  = (const float*)d_in[4];
    const float* user_emb_w      = (const float*)d_in[5];
    const float* item_emb_w      = (const float*)d_in[6];
    float* out = (float*)d_out;

    group_embedding_kernel<<<G_, NTHREADS>>>(
        group_user, behavior_ids, behavior_counts, target_user,
        similarity_vec, user_emb_w, item_emb_w, out);
}

// round 4
// speedup vs baseline: 1.8469x; 1.4131x over previous
#include <cuda_runtime.h>

// Problem constants (from reference)
#define G_ 4096
#define U_ 50
#define M_ 20
#define D_ 64
#define S_ 64
#define FACTOR_ 0.5f

// 25 warps = 50 half-warp slots = exactly one user per slot, single pass.
#define NWARPS 25
#define NTHREADS (NWARPS * 32)   // 800
#define SLOTS (NWARPS * 2)       // 50

__global__ __launch_bounds__(NTHREADS, 2)
void group_embedding_kernel(const int*   __restrict__ group_user,      // [G,U]
                            const int*   __restrict__ behavior_ids,    // [G,U,M]
                            const float* __restrict__ behavior_counts, // [G,U,M]
                            const int*   __restrict__ target_user,     // [G]
                            const float* __restrict__ similarity_vec,  // [100000,S]
                            const float* __restrict__ user_emb_w,      // [100000,D]
                            const float* __restrict__ item_emb_w,      // [100000,D]
                            float*       __restrict__ out)             // [G,D]
{
    const int g    = blockIdx.x;
    const int tid  = threadIdx.x;
    const int warp = tid >> 5;
    const int lane = tid & 31;
    const int half = lane >> 4;     // which user of the warp's pair
    const int hl   = lane & 15;     // lane within half-warp: owns dims 4*hl..4*hl+3
    const int slot = warp * 2 + half;   // 0..49 == user index, single pass

    __shared__ __align__(16) float  partials[SLOTS][D_]; // 12.8KB
    __shared__ __align__(16) float2 beh[U_ * M_];        // packed (id_as_float, count), 8KB

    // ---- Stage behavior (id,count) pairs into smem (coalesced) ----
    {
        const int base = g * (U_ * M_);
        for (int i = tid; i < U_ * M_; i += NTHREADS) {
            beh[i] = make_float2(__int_as_float(behavior_ids[base + i]),
                                 behavior_counts[base + i]);
        }
    }

    // This half-warp's user id (all 16 lanes same address -> broadcast sector).
    const int uid = group_user[g * U_ + slot];

    // Target similarity vector: each half-lane holds 4 consecutive dims.
    const int tgt = target_user[g];
    const float4 tsim = *reinterpret_cast<const float4*>(
        similarity_vec + (size_t)tgt * S_ + 4 * hl);

    // sim = FACTOR * dot(target_sim, other_sim), reduced over the half-warp.
    const float4 osim = *reinterpret_cast<const float4*>(
        similarity_vec + (size_t)uid * S_ + 4 * hl);
    float dot = tsim.x * osim.x + tsim.y * osim.y
              + tsim.z * osim.z + tsim.w * osim.w;
    #pragma unroll
    for (int o = 8; o; o >>= 1)
        dot += __shfl_xor_sync(0xffffffffu, dot, o);
    const float sim = FACTOR_ * dot;

    __syncthreads();   // beh[] ready

    // Weighted sum of item embeddings: 20 independent float4 gathers.
    float4 ub = make_float4(0.f, 0.f, 0.f, 0.f);
    const int bbase = slot * M_;
    #pragma unroll
    for (int m = 0; m < M_; m++) {
        const float2 p  = beh[bbase + m];       // LDS.64 broadcast per half
        const int    id = __float_as_int(p.x);
        const float  c  = p.y;
        const float4 e  = *reinterpret_cast<const float4*>(
            item_emb_w + (size_t)id * D_ + 4 * hl);
        ub.x += e.x * c;  ub.y += e.y * c;
        ub.z += e.z * c;  ub.w += e.w * c;
    }

    // Personalize with user embedding, weight by sim.
    const float4 ue = *reinterpret_cast<const float4*>(
        user_emb_w + (size_t)uid * D_ + 4 * hl);
    float4 acc;
    acc.x = ub.x * ue.x * sim;
    acc.y = ub.y * ue.y * sim;
    acc.z = ub.z * ue.z * sim;
    acc.w = ub.w * ue.w * sim;

    *reinterpret_cast<float4*>(&partials[slot][4 * hl]) = acc;
    __syncthreads();

    // Deterministic cross-slot tree sum: threads 0..63 each own one dim.
    if (tid < D_) {
        float s = 0.f;
        #pragma unroll
        for (int w = 0; w < SLOTS; w++)
            s += partials[w][tid];
        out[(size_t)g * D_ + tid] = s;
    }
}

extern "C" void kernel_launch(void* const* d_in, const int* in_sizes, int n_in,
                              void* d_out, int out_size) {
    const int*   group_user      = (const int*)  d_in[0];
    const int*   behavior_ids    = (const int*)  d_in[1];
    const float* behavior_counts = (const float*)d_in[2];
    const int*   target_user     = (const int*)  d_in[3];
    const float* similarity_vec  = (const float*)d_in[4];
    const float* user_emb_w      = (const float*)d_in[5];
    const float* item_emb_w      = (const float*)d_in[6];
    float* out = (float*)d_out;

    group_embedding_kernel<<<G_, NTHREADS>>>(
        group_user, behavior_ids, behavior_counts, target_user,
        similarity_vec, user_emb_w, item_emb_w, out);
}

// round 5
// speedup vs baseline: 2.0173x; 1.0923x over previous
#include <cuda_runtime.h>

// Problem constants (from reference)
#define G_ 4096
#define U_ 50
#define M_ 20
#define D_ 64
#define S_ 64
#define FACTOR_ 0.5f

// 25 warps = 50 half-warp slots = exactly one user per slot, single pass.
#define NWARPS 25
#define NTHREADS (NWARPS * 32)   // 800
#define SLOTS (NWARPS * 2)       // 50

__global__ __launch_bounds__(NTHREADS, 2)
void group_embedding_kernel(const int*   __restrict__ group_user,      // [G,U]
                            const int*   __restrict__ behavior_ids,    // [G,U,M]
                            const float* __restrict__ behavior_counts, // [G,U,M]
                            const int*   __restrict__ target_user,     // [G]
                            const float* __restrict__ similarity_vec,  // [100000,S]
                            const float* __restrict__ user_emb_w,      // [100000,D]
                            const float* __restrict__ item_emb_w,      // [100000,D]
                            float*       __restrict__ out)             // [G,D]
{
    const int g    = blockIdx.x;
    const int tid  = threadIdx.x;
    const int warp = tid >> 5;
    const int lane = tid & 31;
    const int half = lane >> 4;     // which user of the warp's pair
    const int hl   = lane & 15;     // lane within half-warp: owns dims 4*hl..4*hl+3
    const int slot = warp * 2 + half;   // 0..49 == user index, single pass

    __shared__ __align__(16) float  partials[SLOTS][D_];  // 12.8KB
    __shared__ __align__(16) float  red[8][D_];           // 2KB, stage-1 reduce
    __shared__ __align__(16) float2 wbeh[NWARPS][2 * M_]; // per-warp (id,count), 8KB

    // ---- Per-warp staging: this warp's 2 users' 40 (id,count) pairs.
    // Global pairs [g*1000 + 40*warp, +40) are contiguous -> coalesced LDG.
    {
        const int base = g * (U_ * M_) + warp * (2 * M_);
        wbeh[warp][lane] = make_float2(__int_as_float(behavior_ids[base + lane]),
                                       behavior_counts[base + lane]);
        if (lane < 8)
            wbeh[warp][32 + lane] =
                make_float2(__int_as_float(behavior_ids[base + 32 + lane]),
                            behavior_counts[base + 32 + lane]);
    }

    // This half-warp's user id (all 16 lanes same address -> broadcast sector).
    const int uid = group_user[g * U_ + slot];

    // Issue the user-embedding load early so it overlaps the gather chain.
    const float4 ue = *reinterpret_cast<const float4*>(
        user_emb_w + (size_t)uid * D_ + 4 * hl);

    // Target similarity vector: each half-lane holds 4 consecutive dims.
    const int tgt = target_user[g];
    const float4 tsim = *reinterpret_cast<const float4*>(
        similarity_vec + (size_t)tgt * S_ + 4 * hl);

    // sim = FACTOR * dot(target_sim, other_sim), reduced over the half-warp.
    const float4 osim = *reinterpret_cast<const float4*>(
        similarity_vec + (size_t)uid * S_ + 4 * hl);
    float dot = tsim.x * osim.x + tsim.y * osim.y
              + tsim.z * osim.z + tsim.w * osim.w;
    #pragma unroll
    for (int o = 8; o; o >>= 1)
        dot += __shfl_xor_sync(0xffffffffu, dot, o);
    const float sim = FACTOR_ * dot;

    __syncwarp();   // own warp's wbeh slice ready (no block-wide barrier)

    // Weighted sum of item embeddings: 20 independent float4 gathers.
    float4 ub = make_float4(0.f, 0.f, 0.f, 0.f);
    const int bbase = half * M_;
    #pragma unroll
    for (int m = 0; m < M_; m++) {
        const float2 p  = wbeh[warp][bbase + m];   // LDS.64 broadcast per half
        const int    id = __float_as_int(p.x);
        const float  c  = p.y;
        const float4 e  = *reinterpret_cast<const float4*>(
            item_emb_w + (size_t)id * D_ + 4 * hl);
        ub.x += e.x * c;  ub.y += e.y * c;
        ub.z += e.z * c;  ub.w += e.w * c;
    }

    // Personalize with user embedding, weight by sim.
    float4 acc;
    acc.x = ub.x * ue.x * sim;
    acc.y = ub.y * ue.y * sim;
    acc.z = ub.z * ue.z * sim;
    acc.w = ub.w * ue.w * sim;

    *reinterpret_cast<float4*>(&partials[slot][4 * hl]) = acc;
    __syncthreads();

    // ---- Two-stage deterministic reduce over 50 slots ----
    // Stage 1: 512 threads, 8 rows per dim, each sums slots r, r+8, r+16, ...
    if (tid < 512) {
        const int d = tid & 63;
        const int r = tid >> 6;      // 0..7
        float s = 0.f;
        #pragma unroll
        for (int p = r; p < SLOTS; p += 8)
            s += partials[p][d];
        red[r][d] = s;
    }
    __syncthreads();

    // Stage 2: 64 threads fold the 8 rows.
    if (tid < D_) {
        float s = 0.f;
        #pragma unroll
        for (int r = 0; r < 8; r++)
            s += red[r][tid];
        out[(size_t)g * D_ + tid] = s;
    }
}

extern "C" void kernel_launch(void* const* d_in, const int* in_sizes, int n_in,
                              void* d_out, int out_size) {
    const int*   group_user      = (const int*)  d_in[0];
    const int*   behavior_ids    = (const int*)  d_in[1];
    const float* behavior_counts = (const float*)d_in[2];
    const int*   target_user     = (const int*)  d_in[3];
    const float* similarity_vec  = (const float*)d_in[4];
    const float* user_emb_w      = (const float*)d_in[5];
    const float* item_emb_w      = (const float*)d_in[6];
    float* out = (float*)d_out;

    group_embedding_kernel<<<G_, NTHREADS>>>(
        group_user, behavior_ids, behavior_counts, target_user,
        similarity_vec, user_emb_w, item_emb_w, out);
}